// round 4
// baseline (speedup 1.0000x reference)
#include <cuda_runtime.h>
#include <cuda_bf16.h>

// Problem constants (match reference)
#define GN 512
#define IMG_H 512
#define IMG_W 512
#define BLOCK_H 16
#define BLOCK_W 16
#define TILES_X 32
#define TILES_Y 32

// Per-gaussian precomputed parameters (device scratch; statically allocated)
__device__ float4   g_p0[GN];      // cx, cy, 0.5*ca, cb
__device__ float4   g_p1[GN];      // 0.5*cc, f0*o, f1*o, f2*o
__device__ unsigned g_bounds[GN];  // tminx | tmaxx<<8 | tminy<<16 | tmaxy<<24

__global__ void precompute_kernel(const float* __restrict__ xyz,
                                  const float* __restrict__ chol,
                                  const float* __restrict__ feat,
                                  const float* __restrict__ opac)
{
    // Let the dependent render grid launch immediately; it parks at
    // cudaGridDependencySynchronize() until our memory is visible.
    cudaTriggerProgrammaticLaunchCompletion();

    int i = blockIdx.x * blockDim.x + threadIdx.x;  // grid 4 x 128 = 512
    if (i >= GN) return;

    float2 xy = ((const float2*)xyz)[i];
    float mx = tanhf(xy.x);
    float my = tanhf(xy.y);

    float l0 = chol[3*i + 0] + 0.5f;
    float l1 = chol[3*i + 1];
    float l2 = chol[3*i + 2] + 0.5f;

    float cxx = l0 * l0;
    float cxy = l0 * l1;
    float cyy = l1 * l1 + l2 * l2;
    float det = cxx * cyy - cxy * cxy;
    float inv_det = 1.0f / det;
    float ca = cyy * inv_det;
    float cb = -cxy * inv_det;
    float cc = cxx * inv_det;

    float cx = 0.5f * (float)IMG_W * (mx + 1.0f);
    float cy = 0.5f * (float)IMG_H * (my + 1.0f);

    float b  = 0.5f * (cxx + cyy);
    float v1 = b + sqrtf(fmaxf(b * b - det, 0.1f));
    float radius = ceilf(3.0f * sqrtf(v1));

    int tminx = (int)((cx - radius) * (1.0f / BLOCK_W));
    int tmaxx = (int)((cx + radius) * (1.0f / BLOCK_W)) + 1;
    int tminy = (int)((cy - radius) * (1.0f / BLOCK_H));
    int tmaxy = (int)((cy + radius) * (1.0f / BLOCK_H)) + 1;
    tminx = min(max(tminx, 0), TILES_X);
    tmaxx = min(max(tmaxx, 0), TILES_X);
    tminy = min(max(tminy, 0), TILES_Y);
    tmaxy = min(max(tmaxy, 0), TILES_Y);

    float o = opac[i];
    g_p0[i] = make_float4(cx, cy, 0.5f * ca, cb);
    g_p1[i] = make_float4(0.5f * cc,
                          feat[3*i + 0] * o,
                          feat[3*i + 1] * o,
                          feat[3*i + 2] * o);
    g_bounds[i] = (unsigned)tminx | ((unsigned)tmaxx << 8) |
                  ((unsigned)tminy << 16) | ((unsigned)tmaxy << 24);
}

__global__ __launch_bounds__(256) void render_kernel(float* __restrict__ out)
{
    const int tx = blockIdx.x;   // tile x
    const int ty = blockIdx.y;   // tile y
    const int lx = threadIdx.x;
    const int ly = threadIdx.y;
    const int tid = ly * BLOCK_W + lx;
    const int lane = tid & 31;

    __shared__ float4 s_p0[GN];
    __shared__ float4 s_p1[GN];
    __shared__ int s_count;
    if (tid == 0) s_count = 0;

    // Wait for precompute's writes to become visible.
    cudaGridDependencySynchronize();
    __syncthreads();

    // Phase A: 128 threads test 4 gaussians each from one uint4 load.
    if (tid < 128) {
        uint4 b4 = ((const uint4*)g_bounds)[tid];
        #pragma unroll
        for (int j = 0; j < 4; j++) {
            unsigned b = (j == 0) ? b4.x : (j == 1) ? b4.y : (j == 2) ? b4.z : b4.w;
            bool pred = (tx >= (int)(b & 0xFFu)) &&
                        (tx <  (int)((b >> 8) & 0xFFu)) &&
                        (ty >= (int)((b >> 16) & 0xFFu)) &&
                        (ty <  (int)(b >> 24));
            unsigned m = __ballot_sync(0xffffffffu, pred);
            if (m) {
                int base = 0;
                if (lane == 0) base = atomicAdd(&s_count, __popc(m));
                base = __shfl_sync(0xffffffffu, base, 0);
                if (pred) {
                    int i = tid * 4 + j;
                    int p = base + __popc(m & ((1u << lane) - 1u));
                    s_p0[p] = g_p0[i];
                    s_p1[p] = g_p1[i];
                }
            }
        }
    }
    __syncthreads();
    const int cnt = s_count;

    // Phase B: accumulate survivors for this thread's pixel.
    const float px = (float)(tx * BLOCK_W + lx);
    const float py = (float)(ty * BLOCK_H + ly);

    float acc0 = 0.0f, acc1 = 0.0f, acc2 = 0.0f;
    for (int k = 0; k < cnt; k++) {
        float4 p0 = s_p0[k];   // broadcast LDS
        float4 p1 = s_p1[k];
        float dx = p0.x - px;
        float dy = p0.y - py;
        float sigma = p0.z * dx * dx + p1.x * dy * dy + p0.w * dx * dy;
        float w = __expf(-sigma);
        acc0 += w * p1.y;
        acc1 += w * p1.z;
        acc2 += w * p1.w;
    }

    acc0 = fminf(fmaxf(acc0, 0.0f), 1.0f);
    acc1 = fminf(fmaxf(acc1, 0.0f), 1.0f);
    acc2 = fminf(fmaxf(acc2, 0.0f), 1.0f);

    const int pix = (ty * BLOCK_H + ly) * IMG_W + (tx * BLOCK_W + lx);
    out[0 * IMG_H * IMG_W + pix] = acc0;
    out[1 * IMG_H * IMG_W + pix] = acc1;
    out[2 * IMG_H * IMG_W + pix] = acc2;
}

extern "C" void kernel_launch(void* const* d_in, const int* in_sizes, int n_in,
                              void* d_out, int out_size)
{
    const float* xyz  = (const float*)d_in[0];
    const float* chol = (const float*)d_in[1];
    const float* feat = (const float*)d_in[2];
    const float* opac = (const float*)d_in[3];
    float* out = (float*)d_out;

    precompute_kernel<<<4, 128>>>(xyz, chol, feat, opac);

    // Render with programmatic dependent launch: CTAs pre-launch and park at
    // cudaGridDependencySynchronize() until precompute's memory is visible.
    cudaLaunchConfig_t cfg = {};
    cfg.gridDim  = dim3(TILES_X, TILES_Y, 1);
    cfg.blockDim = dim3(BLOCK_W, BLOCK_H, 1);
    cfg.dynamicSmemBytes = 0;
    cfg.stream = 0;
    cudaLaunchAttribute attrs[1];
    attrs[0].id = cudaLaunchAttributeProgrammaticStreamSerialization;
    attrs[0].val.programmaticStreamSerializationAllowed = 1;
    cfg.attrs = attrs;
    cfg.numAttrs = 1;
    cudaLaunchKernelEx(&cfg, render_kernel, out);
}

// round 5
// speedup vs baseline: 1.0182x; 1.0182x over previous
#include <cuda_runtime.h>
#include <cuda_bf16.h>

#define GN 512
#define IMG_H 512
#define IMG_W 512
#define TILES_X 32
#define TILES_Y 32
// CTA covers a 2x2 tile group = 32x32 pixels. Grid 16x16.
#define GRP 16

// tanh(x) = 1 - 2/(exp(2x)+1)
__device__ __forceinline__ float fast_tanh(float x) {
    return 1.0f - __fdividef(2.0f, __expf(2.0f * x) + 1.0f);
}

__global__ __launch_bounds__(256) void render_grp_kernel(
    const float* __restrict__ xyz,
    const float* __restrict__ chol,
    const float* __restrict__ feat,
    const float* __restrict__ opac,
    float* __restrict__ out)
{
    const int gtx = blockIdx.x;          // tile-group x in [0,16)
    const int gty = blockIdx.y;          // tile-group y in [0,16)
    const int tx0 = gtx * 2;             // first tile column of group
    const int ty0 = gty * 2;             // first tile row of group
    const int lx = threadIdx.x;          // [0,32)
    const int ly = threadIdx.y;          // [0,8)
    const int tid = ly * 32 + lx;
    const int lane = tid & 31;

    __shared__ float4 s_p0[GN];          // cx, cy, 0.5*ca, cb
    __shared__ float4 s_p1[GN];          // 0.5*cc, f0*o, f1*o, f2*o
    __shared__ int    s_m[GN];           // quadrant mask: colbits | rowbits<<2
    __shared__ int s_count;
    if (tid == 0) s_count = 0;
    __syncthreads();

    // Phase A: cull all 512 gaussians against this 2x2 tile group.
    #pragma unroll
    for (int it = 0; it < 2; it++) {
        const int i = tid + it * 256;

        float2 xy = ((const float2*)xyz)[i];
        float l0 = chol[3*i + 0] + 0.5f;
        float l1 = chol[3*i + 1];
        float l2 = chol[3*i + 2] + 0.5f;

        float cx = 256.0f * (fast_tanh(xy.x) + 1.0f);
        float cy = 256.0f * (fast_tanh(xy.y) + 1.0f);

        float cxx = l0 * l0;
        float cxy = l0 * l1;
        float cyy = l1 * l1 + l2 * l2;
        float det = cxx * cyy - cxy * cxy;

        float b  = 0.5f * (cxx + cyy);
        float v1 = fmaxf(b * b - det, 0.1f);
        v1 = b + v1 * rsqrtf(v1);                       // b + sqrt(.)
        float radius = ceilf(3.0f * v1 * rsqrtf(v1));   // ceil(3*sqrt(v1))

        int tminx = (int)((cx - radius) * 0.0625f);
        int tmaxx = (int)((cx + radius) * 0.0625f) + 1;
        int tminy = (int)((cy - radius) * 0.0625f);
        int tmaxy = (int)((cy + radius) * 0.0625f) + 1;

        // Overlap with tile columns {tx0, tx0+1} and rows {ty0, ty0+1}
        bool ovx = (tminx <= tx0 + 1) && (tmaxx > tx0);
        bool ovy = (tminy <= ty0 + 1) && (tmaxy > ty0);
        bool pred = ovx && ovy;

        unsigned m = __ballot_sync(0xffffffffu, pred);
        if (m) {
            int base = 0;
            if (lane == 0) base = atomicAdd(&s_count, __popc(m));
            base = __shfl_sync(0xffffffffu, base, 0);
            if (pred) {
                // quadrant mask
                int cm = ((tminx <= tx0     && tmaxx > tx0    ) ? 1 : 0)
                       | ((tminx <= tx0 + 1 && tmaxx > tx0 + 1) ? 2 : 0);
                int rm = ((tminy <= ty0     && tmaxy > ty0    ) ? 1 : 0)
                       | ((tminy <= ty0 + 1 && tmaxy > ty0 + 1) ? 2 : 0);
                // full params (rare path)
                float inv_det = __fdividef(1.0f, det);
                float ca = cyy * inv_det;
                float cb = -cxy * inv_det;
                float cc = cxx * inv_det;
                float o = opac[i];
                int p = base + __popc(m & ((1u << lane) - 1u));
                s_p0[p] = make_float4(cx, cy, 0.5f * ca, cb);
                s_p1[p] = make_float4(0.5f * cc,
                                      feat[3*i + 0] * o,
                                      feat[3*i + 1] * o,
                                      feat[3*i + 2] * o);
                s_m[p] = cm | (rm << 2);
            }
        }
    }
    __syncthreads();
    const int cnt = s_count;

    // Phase B: 4 pixels per thread (same column, rows strided by 8).
    const float px  = (float)(gtx * 32 + lx);
    const float py0 = (float)(gty * 32 + ly);
    const int   qx  = lx >> 4;   // which tile column of the group

    float a0[4] = {0,0,0,0}, a1[4] = {0,0,0,0}, a2[4] = {0,0,0,0};

    for (int k = 0; k < cnt; k++) {
        float4 p0 = s_p0[k];     // broadcast LDS
        float4 p1 = s_p1[k];
        int    mk = s_m[k];
        float colbit = (float)((mk >> qx) & 1);
        float row0 = colbit * (float)((mk >> 2) & 1);
        float row1 = colbit * (float)((mk >> 3) & 1);

        float dx   = p0.x - px;
        float adx2 = p0.z * dx * dx;   // 0.5*ca*dx^2 (shared by 4 pixels)
        float bdx  = p0.w * dx;        // cb*dx

        #pragma unroll
        for (int j = 0; j < 4; j++) {
            float dy = p0.y - (py0 + (float)(8 * j));
            float sigma = adx2 + p1.x * dy * dy + bdx * dy;
            float inj = (j < 2) ? row0 : row1;   // qy = j>>1
            float w = inj * __expf(-sigma);
            a0[j] += w * p1.y;
            a1[j] += w * p1.z;
            a2[j] += w * p1.w;
        }
    }

    const int gx = gtx * 32 + lx;
    #pragma unroll
    for (int j = 0; j < 4; j++) {
        int pix = (gty * 32 + ly + 8 * j) * IMG_W + gx;
        out[0 * IMG_H * IMG_W + pix] = fminf(fmaxf(a0[j], 0.0f), 1.0f);
        out[1 * IMG_H * IMG_W + pix] = fminf(fmaxf(a1[j], 0.0f), 1.0f);
        out[2 * IMG_H * IMG_W + pix] = fminf(fmaxf(a2[j], 0.0f), 1.0f);
    }
}

extern "C" void kernel_launch(void* const* d_in, const int* in_sizes, int n_in,
                              void* d_out, int out_size)
{
    const float* xyz  = (const float*)d_in[0];
    const float* chol = (const float*)d_in[1];
    const float* feat = (const float*)d_in[2];
    const float* opac = (const float*)d_in[3];
    float* out = (float*)d_out;

    dim3 grid(GRP, GRP);
    dim3 block(32, 8);
    render_grp_kernel<<<grid, block>>>(xyz, chol, feat, opac, out);
}